// round 5
// baseline (speedup 1.0000x reference)
#include <cuda_runtime.h>
#include <math_constants.h>

// Until: out[b,t,x] = min(phi[b,t,x], max(psi[b,t,x], out[b,t-1,x])), out[-1] = -1e6.
// Single-pass chained scan (decoupled lookback) over t. Monoid f(v)=min(A,max(B,v)):
//   compose (later∘earlier): A' = min(A2, max(B2, A1)), B' = max(B1, B2).
// R5: epoch-tagged flags (no reset kernel), TC=512 (chain depth 16),
//     hierarchical warp-parallel fold + distributed slice carries.

#define B_   64
#define T_   8192
#define X_   32
#define TC_  512                // time steps per chunk
#define C_   (T_ / TC_)         // 16 chunks per batch
#define NB_  (B_ * C_)          // 1024 blocks
#define SL_  32                 // t-slices per block
#define PT_  (TC_ / SL_)        // 16 steps per thread
#define NW_  8                  // warps per block
#define SPW_ (SL_ / NW_)        // 4 slices per warp
#define LARGE_ 1.0e6f

__device__ float g_A[NB_ * X_];   // chunk aggregate A
__device__ float g_Bv[NB_ * X_];  // chunk aggregate B
__device__ float g_P[NB_ * X_];   // chunk inclusive prefix value
__device__ int   g_flag[NB_];     // epoch-tagged: 2e+1 aggregate, 2e+2 prefix
__device__ int   g_ticket;        // never reset; epoch = ticket / NB_

__global__ void __launch_bounds__(256) until_scan(const float* __restrict__ phi,
                                                  const float* __restrict__ psi,
                                                  float* __restrict__ out) {
    __shared__ float sA[SL_][X_];
    __shared__ float sB[SL_][X_];
    __shared__ float sWA[NW_][X_];   // per-warp fold of its 4 slices
    __shared__ float sWB[NW_][X_];
    __shared__ float sGC[NW_][X_];   // carry entering each warp's slice group
    __shared__ int s_tic;

    const int tid = threadIdx.x;
    if (tid == 0) s_tic = atomicAdd(&g_ticket, 1);
    __syncthreads();
    const int traw = s_tic;
    const int e    = traw / NB_;          // epoch (graph replay count)
    const int v    = traw - e * NB_;
    const int b    = v % B_;              // breadth-first over chunks
    const int c    = v / B_;
    const int bc   = b * C_ + c;
    const int FLAG_AGG = 2 * e + 1;
    const int FLAG_PRE = 2 * e + 2;

    const int xq   = (tid & 7) * 4;       // 4 consecutive x per thread
    const int s    = tid >> 3;            // slice 0..31
    const int w    = tid >> 5;            // warp 0..7
    const int lane = tid & 31;

    const size_t base = (size_t)b * T_ * X_ + (size_t)(c * TC_ + s * PT_) * X_ + xq;
    const float4* pp = (const float4*)(phi + base);
    const float4* qq = (const float4*)(psi + base);

    // ---------- phase 1: streaming aggregate (no data kept in registers) ----------
    float4 A  = make_float4( CUDART_INF_F,  CUDART_INF_F,  CUDART_INF_F,  CUDART_INF_F);
    float4 Bc = make_float4(-CUDART_INF_F, -CUDART_INF_F, -CUDART_INF_F, -CUDART_INF_F);
#pragma unroll
    for (int i = 0; i < PT_; i++) {
        float4 p = pp[i * (X_ / 4)];
        float4 q = qq[i * (X_ / 4)];
        A.x = fminf(p.x, fmaxf(q.x, A.x));  Bc.x = fmaxf(q.x, Bc.x);
        A.y = fminf(p.y, fmaxf(q.y, A.y));  Bc.y = fmaxf(q.y, Bc.y);
        A.z = fminf(p.z, fmaxf(q.z, A.z));  Bc.z = fmaxf(q.z, Bc.z);
        A.w = fminf(p.w, fmaxf(q.w, A.w));  Bc.w = fmaxf(q.w, Bc.w);
    }
    sA[s][xq + 0] = A.x;  sA[s][xq + 1] = A.y;  sA[s][xq + 2] = A.z;  sA[s][xq + 3] = A.w;
    sB[s][xq + 0] = Bc.x; sB[s][xq + 1] = Bc.y; sB[s][xq + 2] = Bc.z; sB[s][xq + 3] = Bc.w;
    __syncthreads();

    // ---------- fold level 1: each warp folds its 4 slices (lane = x) ----------
    {
        float wA =  CUDART_INF_F;
        float wB = -CUDART_INF_F;
#pragma unroll
        for (int j = 0; j < SPW_; j++) {
            const int sl = w * SPW_ + j;
            wA = fminf(sA[sl][lane], fmaxf(sB[sl][lane], wA));
            wB = fmaxf(sB[sl][lane], wB);
        }
        sWA[w][lane] = wA;
        sWB[w][lane] = wB;
    }
    __syncthreads();

    // ---------- fold level 2 + lookback (warp 0, lane = x) ----------
    if (tid < 32) {
        const int x = tid;
        float Ab =  CUDART_INF_F;
        float Bb = -CUDART_INF_F;
#pragma unroll
        for (int j = 0; j < NW_; j++) {
            Ab = fminf(sWA[j][x], fmaxf(sWB[j][x], Ab));
            Bb = fmaxf(sWB[j][x], Bb);
        }

        // Publish aggregate ONLY for c>0: chunk 0 goes straight to prefix,
        // so lookback never crosses a batch boundary.
        if (c > 0) {
            g_A[bc * X_ + x]  = Ab;
            g_Bv[bc * X_ + x] = Bb;
            __threadfence();
            __syncwarp();
            if (x == 0) *(volatile int*)&g_flag[bc] = FLAG_AGG;
        }

        float vin;
        if (c == 0) {
            vin = -LARGE_;
        } else {
            float accA =  CUDART_INF_F;
            float accB = -CUDART_INF_F;
            int j = bc - 1;
            while (true) {
                int f;
                do { f = *(volatile int*)&g_flag[j]; } while (f < FLAG_AGG);
                __threadfence();
                if (f == FLAG_PRE) {
                    vin = fminf(accA, fmaxf(accB, g_P[j * X_ + x]));
                    break;
                }
                float Aj = g_A[j * X_ + x];
                float Bj = g_Bv[j * X_ + x];
                accA = fminf(accA, fmaxf(accB, Aj));
                accB = fmaxf(accB, Bj);
                j--;
            }
        }

        // carries entering each warp's slice group + publish inclusive prefix
        float g = vin;
#pragma unroll
        for (int j = 0; j < NW_; j++) {
            sGC[j][x] = g;
            g = fminf(sWA[j][x], fmaxf(sWB[j][x], g));
        }
        g_P[bc * X_ + x] = g;
        __threadfence();
        __syncwarp();
        if (x == 0) *(volatile int*)&g_flag[bc] = FLAG_PRE;
    }
    __syncthreads();

    // ---------- per-thread slice carry: push warp-group carry through slices ----------
    const int wbase = w * SPW_;
    float4 vc;
    {
        float v0 = sGC[w][xq + 0];
        float v1 = sGC[w][xq + 1];
        float v2 = sGC[w][xq + 2];
        float v3 = sGC[w][xq + 3];
        for (int j = wbase; j < s; j++) {
            v0 = fminf(sA[j][xq + 0], fmaxf(sB[j][xq + 0], v0));
            v1 = fminf(sA[j][xq + 1], fmaxf(sB[j][xq + 1], v1));
            v2 = fminf(sA[j][xq + 2], fmaxf(sB[j][xq + 2], v2));
            v3 = fminf(sA[j][xq + 3], fmaxf(sB[j][xq + 3], v3));
        }
        vc = make_float4(v0, v1, v2, v3);
    }

    // ---------- phase 2: reload (L2 hits), apply carry, stream out ----------
    float4* oo = (float4*)(out + base);
#pragma unroll
    for (int i = 0; i < PT_; i++) {
        float4 p = __ldcs(&pp[i * (X_ / 4)]);
        float4 q = __ldcs(&qq[i * (X_ / 4)]);
        vc.x = fminf(p.x, fmaxf(q.x, vc.x));
        vc.y = fminf(p.y, fmaxf(q.y, vc.y));
        vc.z = fminf(p.z, fmaxf(q.z, vc.z));
        vc.w = fminf(p.w, fmaxf(q.w, vc.w));
        __stcs(&oo[i * (X_ / 4)], vc);
    }
}

extern "C" void kernel_launch(void* const* d_in, const int* in_sizes, int n_in,
                              void* d_out, int out_size) {
    const float* phi = (const float*)d_in[0];
    const float* psi = (const float*)d_in[1];
    float* out = (float*)d_out;

    until_scan<<<NB_, 256>>>(phi, psi, out);
}